// round 14
// baseline (speedup 1.0000x reference)
#include <cuda_runtime.h>

#define NB 8
#define NV 100000
#define NF 200000
#define BN (NB * NV)
#define TOTF (NB * NF)
#define PAIRS (TOTF / 2)

#define GRID_BLOCKS 592   // 4 per SM x 148 SMs; GB300 has 152 SMs -> all resident
#define NTHREADS (GRID_BLOCKS * 256)

// scratch: per-vertex accumulator (x, y, z, deg) — 12.8 MB, L2-resident
__device__ float4 g_acc[BN];
// padded, 16B-aligned copy of V for single-LDG.128 gathers
__device__ float4 g_V4[BN];
__device__ int g_is32;       // 1 if F is int32, 0 if int64
// grid barrier state — self-restores to (0,0) after two barriers per launch
__device__ unsigned g_cnt = 0;
__device__ unsigned g_sense = 0;

// Sense-reversing grid barrier. All GRID_BLOCKS blocks must be co-resident
// (guaranteed by __launch_bounds__(256, 4) occupancy + grid size).
__device__ __forceinline__ void grid_barrier(unsigned want) {
    __syncthreads();
    if (threadIdx.x == 0) {
        __threadfence();  // make this block's prior writes (incl. REDs) visible
        unsigned t = atomicAdd(&g_cnt, 1u);
        if (t == GRID_BLOCKS - 1) {
            g_cnt = 0;
            __threadfence();
            atomicExch(&g_sense, want);
        } else {
            while (atomicAdd(&g_sense, 0u) != want) { }
        }
        __threadfence();
    }
    __syncthreads();
}

__device__ __forceinline__ int clampi(int v, int lo, int hi) {
    return v < lo ? lo : (v > hi ? hi : v);
}

__device__ __forceinline__ void red_v4(float4* addr, float x, float y, float z, float w) {
    asm volatile("red.global.add.v4.f32 [%0], {%1, %2, %3, %4};"
                 :: "l"(addr), "f"(x), "f"(y), "f"(z), "f"(w)
                 : "memory");
}

// Core per-face computation: gathers already in registers.
__device__ __forceinline__ void face_body(int i0, int i1, int i2,
                                          float4 P0, float4 P1, float4 P2) {
    float x0 = P0.x, y0 = P0.y, z0 = P0.z;
    float x1 = P1.x, y1 = P1.y, z1 = P1.z;
    float x2 = P2.x, y2 = P2.y, z2 = P2.z;

    float ax = x1 - x2, ay = y1 - y2, az = z1 - z2;
    float bx = x2 - x0, by = y2 - y0, bz = z2 - z0;
    float cx = x0 - x1, cy = y0 - y1, cz = z0 - z1;
    float d1 = ax * ax + ay * ay + az * az;
    float d2 = bx * bx + by * by + bz * bz;
    float d3 = cx * cx + cy * cy + cz * cz;
    float l1 = sqrtf(d1), l2 = sqrtf(d2), l3 = sqrtf(d3);
    float sp = 0.5f * (l1 + l2 + l3);
    float inside = sp * (sp - l1) * (sp - l2) * (sp - l3);
    inside = fmaxf(inside, 0.0f);
    float A = 2.0f * sqrtf(inside);
    float inv = 0.25f / (A + 1e-10f);
    if (A == 0.0f) inv = 0.0f;

    float w23 = (d2 + d3 - d1) * inv;  // edge (v1,v2)
    float w31 = (d1 + d3 - d2) * inv;  // edge (v2,v0)
    float w12 = (d1 + d2 - d3) * inv;  // edge (v0,v1)

    red_v4(&g_acc[i0], w31 * x2 + w12 * x1, w31 * y2 + w12 * y1,
                       w31 * z2 + w12 * z1, w31 + w12);
    red_v4(&g_acc[i1], w23 * x2 + w12 * x0, w23 * y2 + w12 * y0,
                       w23 * z2 + w12 * z0, w23 + w12);
    red_v4(&g_acc[i2], w23 * x1 + w31 * x0, w23 * y1 + w31 * y0,
                       w23 * z1 + w31 * z0, w23 + w31);
}

// One fused persistent kernel: prep | barrier | faces | barrier | finalize.
__global__ void __launch_bounds__(256, 4) cotlap_k(const float* __restrict__ V,
                                                   const void* __restrict__ Fraw,
                                                   float* __restrict__ out,
                                                   int nwords) {
    int tid = blockIdx.x * blockDim.x + threadIdx.x;

    // ---- Phase 0: dtype detect (block 0, warp 0) ----
    if (blockIdx.x == 0 && threadIdx.x < 32) {
        const long long* F64 = (const long long*)Fraw;
        int lane = threadIdx.x;
        int bad = 0;
        int n = nwords < 1024 ? nwords : 1024;
        #pragma unroll
        for (int k = 0; k < 32; k++) {
            int i = lane + k * 32;
            if (i < n) {
                long long x = F64[i];
                bad |= (x < 0 || x >= NV) ? 1 : 0;
            }
        }
        unsigned m = __ballot_sync(0xFFFFFFFFu, bad);
        if (lane == 0) g_is32 = (m != 0) ? 1 : 0;
    }

    // ---- Phase 1: stage V into float4 + zero accumulators ----
    for (int v = tid; v < BN; v += NTHREADS) {
        const float* p = V + (size_t)v * 3;
        g_V4[v] = make_float4(p[0], p[1], p[2], 0.f);
        g_acc[v] = make_float4(0.f, 0.f, 0.f, 0.f);
    }

    grid_barrier(1u);

    // ---- Phase 2: faces (2 per iteration; pair never straddles a batch) ----
    {
        int is32 = g_is32;
        for (int p = tid; p < PAIRS; p += NTHREADS) {
            int base = (p / (NF / 2)) * NV;

            int fa0, fa1, fa2, fb0, fb1, fb2;
            if (is32) {
                const int2* fp = (const int2*)Fraw + (size_t)p * 3;
                int2 q0 = __ldg(&fp[0]);
                int2 q1 = __ldg(&fp[1]);
                int2 q2 = __ldg(&fp[2]);
                fa0 = q0.x; fa1 = q0.y; fa2 = q1.x;
                fb0 = q1.y; fb1 = q2.x; fb2 = q2.y;
            } else {
                const longlong2* fp = (const longlong2*)Fraw + (size_t)p * 3;
                longlong2 q0 = __ldg(&fp[0]);
                longlong2 q1 = __ldg(&fp[1]);
                longlong2 q2 = __ldg(&fp[2]);
                fa0 = (int)q0.x; fa1 = (int)q0.y; fa2 = (int)q1.x;
                fb0 = (int)q1.y; fb1 = (int)q2.x; fb2 = (int)q2.y;
            }
            fa0 = clampi(fa0, 0, NV - 1); fa1 = clampi(fa1, 0, NV - 1); fa2 = clampi(fa2, 0, NV - 1);
            fb0 = clampi(fb0, 0, NV - 1); fb1 = clampi(fb1, 0, NV - 1); fb2 = clampi(fb2, 0, NV - 1);

            int ia0 = base + fa0, ia1 = base + fa1, ia2 = base + fa2;
            int ib0 = base + fb0, ib1 = base + fb1, ib2 = base + fb2;

            float4 A0 = __ldg(&g_V4[ia0]);
            float4 A1 = __ldg(&g_V4[ia1]);
            float4 A2 = __ldg(&g_V4[ia2]);
            float4 B0 = __ldg(&g_V4[ib0]);
            float4 B1 = __ldg(&g_V4[ib1]);
            float4 B2 = __ldg(&g_V4[ib2]);

            face_body(ia0, ia1, ia2, A0, A1, A2);
            face_body(ib0, ib1, ib2, B0, B1, B2);
        }
    }

    grid_barrier(0u);

    // ---- Phase 3: finalize out[v] = acc.xyz - acc.w * V[v] ----
    for (int v = tid; v < BN; v += NTHREADS) {
        float4 a = g_acc[v];
        float4 p = g_V4[v];
        float* o = out + (size_t)v * 3;
        o[0] = a.x - a.w * p.x;
        o[1] = a.y - a.w * p.y;
        o[2] = a.z - a.w * p.z;
    }
}

extern "C" void kernel_launch(void* const* d_in, const int* in_sizes, int n_in,
                              void* d_out, int out_size) {
    // Robust slot selection: V has BN*3 = 2.4M elements, F has TOTF*3 = 4.8M.
    const float* V;
    const void* F;
    int f_elems;
    if (in_sizes[0] == BN * 3) {
        V = (const float*)d_in[0];
        F = d_in[1];
        f_elems = in_sizes[1];
    } else {
        V = (const float*)d_in[1];
        F = d_in[0];
        f_elems = in_sizes[0];
    }
    float* out = (float*)d_out;

    cotlap_k<<<GRID_BLOCKS, 256>>>(V, F, out, f_elems / 2);
}

// round 15
// speedup vs baseline: 1.0665x; 1.0665x over previous
#include <cuda_runtime.h>

#define NB 8
#define NV 100000
#define NF 200000
#define BN (NB * NV)
#define TOTF (NB * NF)
#define QUADS (TOTF / 4)   // 400000; NF % 4 == 0 so quads never straddle a batch

// scratch: per-vertex accumulator (x, y, z, deg) — 12.8 MB, L2-resident
__device__ float4 g_acc[BN];
// padded, 16B-aligned copy of V for single-LDG.128 gathers
__device__ float4 g_V4[BN];
__device__ int g_is32;   // 1 if F is int32, 0 if int64

// Prep: dtype detect (parallel) + zero accumulators + pad V into float4.
__global__ void __launch_bounds__(256) prep_k(const float* __restrict__ V,
                                              const long long* __restrict__ F64,
                                              int nwords) {
    int v = blockIdx.x * blockDim.x + threadIdx.x;

    if (blockIdx.x == 0 && threadIdx.x < 32) {
        int lane = threadIdx.x;
        int bad = 0;
        int n = nwords < 1024 ? nwords : 1024;
        #pragma unroll
        for (int k = 0; k < 32; k++) {
            int i = lane + k * 32;
            if (i < n) {
                long long x = F64[i];
                bad |= (x < 0 || x >= NV) ? 1 : 0;
            }
        }
        unsigned m = __ballot_sync(0xFFFFFFFFu, bad);
        if (lane == 0) g_is32 = (m != 0) ? 1 : 0;
    }

    if (v >= BN) return;
    const float* p = V + (size_t)v * 3;
    // V is read exactly once across the whole launch -> streaming loads
    float x = __ldcs(&p[0]);
    float y = __ldcs(&p[1]);
    float z = __ldcs(&p[2]);
    g_V4[v] = make_float4(x, y, z, 0.f);
    g_acc[v] = make_float4(0.f, 0.f, 0.f, 0.f);
}

__device__ __forceinline__ int clampi(int v, int lo, int hi) {
    return v < lo ? lo : (v > hi ? hi : v);
}

__device__ __forceinline__ void red_v4(float4* addr, float x, float y, float z, float w) {
    asm volatile("red.global.add.v4.f32 [%0], {%1, %2, %3, %4};"
                 :: "l"(addr), "f"(x), "f"(y), "f"(z), "f"(w)
                 : "memory");
}

// Core per-face computation: gathers already in registers.
__device__ __forceinline__ void face_body(int i0, int i1, int i2,
                                          float4 P0, float4 P1, float4 P2) {
    float x0 = P0.x, y0 = P0.y, z0 = P0.z;
    float x1 = P1.x, y1 = P1.y, z1 = P1.z;
    float x2 = P2.x, y2 = P2.y, z2 = P2.z;

    float ax = x1 - x2, ay = y1 - y2, az = z1 - z2;
    float bx = x2 - x0, by = y2 - y0, bz = z2 - z0;
    float cx = x0 - x1, cy = y0 - y1, cz = z0 - z1;
    float d1 = ax * ax + ay * ay + az * az;
    float d2 = bx * bx + by * by + bz * bz;
    float d3 = cx * cx + cy * cy + cz * cz;
    float l1 = sqrtf(d1), l2 = sqrtf(d2), l3 = sqrtf(d3);
    float sp = 0.5f * (l1 + l2 + l3);
    float inside = sp * (sp - l1) * (sp - l2) * (sp - l3);
    inside = fmaxf(inside, 0.0f);
    float A = 2.0f * sqrtf(inside);
    float inv = 0.25f / (A + 1e-10f);
    if (A == 0.0f) inv = 0.0f;

    float w23 = (d2 + d3 - d1) * inv;  // edge (v1,v2)
    float w31 = (d1 + d3 - d2) * inv;  // edge (v2,v0)
    float w12 = (d1 + d2 - d3) * inv;  // edge (v0,v1)

    red_v4(&g_acc[i0], w31 * x2 + w12 * x1, w31 * y2 + w12 * y1,
                       w31 * z2 + w12 * z1, w31 + w12);
    red_v4(&g_acc[i1], w23 * x2 + w12 * x0, w23 * y2 + w12 * y0,
                       w23 * z2 + w12 * z0, w23 + w12);
    red_v4(&g_acc[i2], w23 * x1 + w31 * x0, w23 * y1 + w31 * y0,
                       w23 * z1 + w31 * z0, w23 + w31);
}

// Four faces per thread: 16B-aligned index loads (int4 / longlong2) and
// 12 independent gathers issued before any compute (max MLP).
__global__ void __launch_bounds__(256) face_k(const void* __restrict__ Fraw) {
    int q = blockIdx.x * blockDim.x + threadIdx.x;
    if (q >= QUADS) return;
    int base = (q / (NF / 4)) * NV;   // quad never straddles a batch (NF%4==0)

    int f[12];
    if (g_is32) {
        // 12 int32 = 48B at offset 48q -> 16B aligned: three int4 loads
        const int4* fp = (const int4*)Fraw + (size_t)q * 3;
        int4 q0 = __ldcs(&fp[0]);
        int4 q1 = __ldcs(&fp[1]);
        int4 q2 = __ldcs(&fp[2]);
        f[0] = q0.x; f[1] = q0.y; f[2]  = q0.z; f[3]  = q0.w;
        f[4] = q1.x; f[5] = q1.y; f[6]  = q1.z; f[7]  = q1.w;
        f[8] = q2.x; f[9] = q2.y; f[10] = q2.z; f[11] = q2.w;
    } else {
        // 12 int64 = 96B at offset 96q -> 16B aligned: six longlong2 loads
        const longlong2* fp = (const longlong2*)Fraw + (size_t)q * 6;
        #pragma unroll
        for (int k = 0; k < 6; k++) {
            longlong2 w = __ldcs(&fp[k]);
            f[2 * k]     = (int)w.x;
            f[2 * k + 1] = (int)w.y;
        }
    }
    int idx[12];
    #pragma unroll
    for (int k = 0; k < 12; k++) idx[k] = base + clampi(f[k], 0, NV - 1);

    // issue all 12 gathers before any compute
    float4 P[12];
    #pragma unroll
    for (int k = 0; k < 12; k++) P[k] = __ldg(&g_V4[idx[k]]);

    #pragma unroll
    for (int m = 0; m < 4; m++)
        face_body(idx[3 * m], idx[3 * m + 1], idx[3 * m + 2],
                  P[3 * m], P[3 * m + 1], P[3 * m + 2]);
}

// out[v] = acc[v].xyz - acc[v].w * V[v]; streaming stores (out never re-read).
__global__ void __launch_bounds__(256) fin_k(float* __restrict__ out) {
    int v = blockIdx.x * blockDim.x + threadIdx.x;
    if (v < BN) {
        float4 a = g_acc[v];
        float4 p = g_V4[v];
        float* o = out + (size_t)v * 3;
        __stcs(&o[0], a.x - a.w * p.x);
        __stcs(&o[1], a.y - a.w * p.y);
        __stcs(&o[2], a.z - a.w * p.z);
    }
}

extern "C" void kernel_launch(void* const* d_in, const int* in_sizes, int n_in,
                              void* d_out, int out_size) {
    // Robust slot selection: V has BN*3 = 2.4M elements, F has TOTF*3 = 4.8M.
    const float* V;
    const void* F;
    int f_elems;
    if (in_sizes[0] == BN * 3) {
        V = (const float*)d_in[0];
        F = d_in[1];
        f_elems = in_sizes[1];
    } else {
        V = (const float*)d_in[1];
        F = d_in[0];
        f_elems = in_sizes[0];
    }
    float* out = (float*)d_out;

    prep_k<<<(BN + 255) / 256, 256>>>(V, (const long long*)F, f_elems / 2);
    face_k<<<(QUADS + 255) / 256, 256>>>(F);
    fin_k<<<(BN + 255) / 256, 256>>>(out);
}

// round 16
// speedup vs baseline: 1.1161x; 1.0464x over previous
#include <cuda_runtime.h>

#define NB 8
#define NV 100000
#define NF 200000
#define BN (NB * NV)
#define TOTF (NB * NF)
#define PAIRS (TOTF / 2)

// scratch: per-vertex accumulator (dx, dy, dz, unused) — 12.8 MB, L2-resident.
// Accumulates w * (V[other] - V[self]) per edge contribution (differential
// form), so finalize needs no V read: out[v] = acc[v].xyz.
__device__ float4 g_acc[BN];
// padded, 16B-aligned copy of V for single-LDG.128 gathers
__device__ float4 g_V4[BN];
__device__ int g_is32;   // 1 if F is int32, 0 if int64

// Prep: dtype detect (parallel) + zero accumulators + pad V into float4.
__global__ void __launch_bounds__(256) prep_k(const float* __restrict__ V,
                                              const long long* __restrict__ F64,
                                              int nwords) {
    int v = blockIdx.x * blockDim.x + threadIdx.x;

    if (blockIdx.x == 0 && threadIdx.x < 32) {
        int lane = threadIdx.x;
        int bad = 0;
        int n = nwords < 1024 ? nwords : 1024;
        #pragma unroll
        for (int k = 0; k < 32; k++) {
            int i = lane + k * 32;
            if (i < n) {
                long long x = F64[i];
                bad |= (x < 0 || x >= NV) ? 1 : 0;
            }
        }
        unsigned m = __ballot_sync(0xFFFFFFFFu, bad);
        if (lane == 0) g_is32 = (m != 0) ? 1 : 0;
    }

    if (v >= BN) return;
    const float* p = V + (size_t)v * 3;
    g_V4[v] = make_float4(p[0], p[1], p[2], 0.f);
    g_acc[v] = make_float4(0.f, 0.f, 0.f, 0.f);
}

__device__ __forceinline__ int clampi(int v, int lo, int hi) {
    return v < lo ? lo : (v > hi ? hi : v);
}

__device__ __forceinline__ void red_v4(float4* addr, float x, float y, float z, float w) {
    asm volatile("red.global.add.v4.f32 [%0], {%1, %2, %3, %4};"
                 :: "l"(addr), "f"(x), "f"(y), "f"(z), "f"(w)
                 : "memory");
}

// Core per-face computation (differential form): for each vertex, accumulate
// w_edge * (V[other] - V[self]) over its two incident edges.
__device__ __forceinline__ void face_body(int i0, int i1, int i2,
                                          float4 P0, float4 P1, float4 P2) {
    float x0 = P0.x, y0 = P0.y, z0 = P0.z;
    float x1 = P1.x, y1 = P1.y, z1 = P1.z;
    float x2 = P2.x, y2 = P2.y, z2 = P2.z;

    // edge vectors (also used for squared lengths)
    float ax = x1 - x2, ay = y1 - y2, az = z1 - z2;  // v1 - v2
    float bx = x2 - x0, by = y2 - y0, bz = z2 - z0;  // v2 - v0
    float cx = x0 - x1, cy = y0 - y1, cz = z0 - z1;  // v0 - v1
    float d1 = ax * ax + ay * ay + az * az;
    float d2 = bx * bx + by * by + bz * bz;
    float d3 = cx * cx + cy * cy + cz * cz;
    float l1 = sqrtf(d1), l2 = sqrtf(d2), l3 = sqrtf(d3);
    float sp = 0.5f * (l1 + l2 + l3);
    float inside = sp * (sp - l1) * (sp - l2) * (sp - l3);
    inside = fmaxf(inside, 0.0f);
    float A = 2.0f * sqrtf(inside);
    float inv = 0.25f / (A + 1e-10f);
    if (A == 0.0f) inv = 0.0f;

    float w23 = (d2 + d3 - d1) * inv;  // edge (v1,v2)
    float w31 = (d1 + d3 - d2) * inv;  // edge (v2,v0)
    float w12 = (d1 + d2 - d3) * inv;  // edge (v0,v1)

    // v0: w31*(v2-v0) + w12*(v1-v0) = w31*b - w12*c
    red_v4(&g_acc[i0], w31 * bx - w12 * cx, w31 * by - w12 * cy,
                       w31 * bz - w12 * cz, 0.f);
    // v1: w23*(v2-v1) + w12*(v0-v1) = -w23*a + w12*c
    red_v4(&g_acc[i1], w12 * cx - w23 * ax, w12 * cy - w23 * ay,
                       w12 * cz - w23 * az, 0.f);
    // v2: w23*(v1-v2) + w31*(v0-v2) = w23*a - w31*b
    red_v4(&g_acc[i2], w23 * ax - w31 * bx, w23 * ay - w31 * by,
                       w23 * az - w31 * bz, 0.f);
}

// Two faces per thread: 16B/8B-aligned index loads + 6 gathers in flight.
__global__ void __launch_bounds__(256) face_k(const void* __restrict__ Fraw) {
    int t = blockIdx.x * blockDim.x + threadIdx.x;
    if (t >= PAIRS) return;
    int base = (t / (NF / 2)) * NV;   // pair never straddles a batch (NF even)

    int fa0, fa1, fa2, fb0, fb1, fb2;
    if (g_is32) {
        // 6 int32 = 24B at offset 24t (8B aligned): three int2 loads
        const int2* fp = (const int2*)Fraw + (size_t)t * 3;
        int2 q0 = __ldg(&fp[0]);
        int2 q1 = __ldg(&fp[1]);
        int2 q2 = __ldg(&fp[2]);
        fa0 = q0.x; fa1 = q0.y; fa2 = q1.x;
        fb0 = q1.y; fb1 = q2.x; fb2 = q2.y;
    } else {
        // 6 int64 = 48B at offset 48t (16B aligned): three longlong2 loads
        const longlong2* fp = (const longlong2*)Fraw + (size_t)t * 3;
        longlong2 q0 = __ldg(&fp[0]);
        longlong2 q1 = __ldg(&fp[1]);
        longlong2 q2 = __ldg(&fp[2]);
        fa0 = (int)q0.x; fa1 = (int)q0.y; fa2 = (int)q1.x;
        fb0 = (int)q1.y; fb1 = (int)q2.x; fb2 = (int)q2.y;
    }
    fa0 = clampi(fa0, 0, NV - 1); fa1 = clampi(fa1, 0, NV - 1); fa2 = clampi(fa2, 0, NV - 1);
    fb0 = clampi(fb0, 0, NV - 1); fb1 = clampi(fb1, 0, NV - 1); fb2 = clampi(fb2, 0, NV - 1);

    int ia0 = base + fa0, ia1 = base + fa1, ia2 = base + fa2;
    int ib0 = base + fb0, ib1 = base + fb1, ib2 = base + fb2;

    float4 A0 = __ldg(&g_V4[ia0]);
    float4 A1 = __ldg(&g_V4[ia1]);
    float4 A2 = __ldg(&g_V4[ia2]);
    float4 B0 = __ldg(&g_V4[ib0]);
    float4 B1 = __ldg(&g_V4[ib1]);
    float4 B2 = __ldg(&g_V4[ib2]);

    face_body(ia0, ia1, ia2, A0, A1, A2);
    face_body(ib0, ib1, ib2, B0, B1, B2);
}

// out[v] = acc[v].xyz — no V read needed (differential accumulation).
__global__ void __launch_bounds__(256) fin_k(float* __restrict__ out) {
    int v = blockIdx.x * blockDim.x + threadIdx.x;
    if (v < BN) {
        float4 a = g_acc[v];
        float* o = out + (size_t)v * 3;
        o[0] = a.x;
        o[1] = a.y;
        o[2] = a.z;
    }
}

extern "C" void kernel_launch(void* const* d_in, const int* in_sizes, int n_in,
                              void* d_out, int out_size) {
    // Robust slot selection: V has BN*3 = 2.4M elements, F has TOTF*3 = 4.8M.
    const float* V;
    const void* F;
    int f_elems;
    if (in_sizes[0] == BN * 3) {
        V = (const float*)d_in[0];
        F = d_in[1];
        f_elems = in_sizes[1];
    } else {
        V = (const float*)d_in[1];
        F = d_in[0];
        f_elems = in_sizes[0];
    }
    float* out = (float*)d_out;

    prep_k<<<(BN + 255) / 256, 256>>>(V, (const long long*)F, f_elems / 2);
    face_k<<<(PAIRS + 255) / 256, 256>>>(F);
    fin_k<<<(BN + 255) / 256, 256>>>(out);
}